// round 17
// baseline (speedup 1.0000x reference)
#include <cuda_runtime.h>
#include <cuda_fp16.h>

#define N_NODES 100000
#define N_EDGES 3200000
#define F_IN    128
#define H       32
#define C_OUT   8
#define B_GR    128
#define BN_EPS  1e-5f
#define FULL    0xffffffffu
#define NBLK    444      // grid for proj kernels
#define NBLK_M  592      // 4 blocks/SM * 148 for k_mlp

// ---------------- scratch (no cudaMalloc allowed) ----------------
__device__ uint4  d_yh[N_NODES * (H / 8)];   // projected features fp16 (gather), 64B/row
__device__ __half d_hA[N_NODES * H];         // ping (fp16)
__device__ __half d_hB[N_NODES * H];         // pong (fp16)
__device__ int    d_counts[N_NODES];         // degree (by dst)
__device__ int    d_cursor[N_NODES];         // scan / scatter cursors (post-scatter: row end)
__device__ int    d_col[N_EDGES];            // CSR column (src) indices
__device__ float  d_sum[4][H];
__device__ float  d_sq[4][H];
__device__ float  d_pooled[B_GR * H];
__device__ float  d_cnt[B_GR];
__device__ float  d_Wf[H * H];               // folded (BN-absorbed) W1 for next layer
__device__ float  d_cf[H];
__device__ float  d_A3[H];
__device__ float  d_Bc3[H];

// ---------------- init ----------------
__global__ void k_zero() {
    int i = blockIdx.x * blockDim.x + threadIdx.x;
    if (i < N_NODES) d_counts[i] = 0;
    if (i < 4 * H) { ((float*)d_sum)[i] = 0.f; ((float*)d_sq)[i] = 0.f; }
    if (i < B_GR * H) d_pooled[i] = 0.f;
    if (i < B_GR) d_cnt[i] = 0.f;
}

// ---------------- CSR build ----------------
__global__ void k_hist(const int* __restrict__ dst) {
    int e4 = blockIdx.x * blockDim.x + threadIdx.x;
    if (e4 * 4 < N_EDGES) {
        int4 v = ((const int4*)dst)[e4];
        atomicAdd(&d_counts[v.x], 1);
        atomicAdd(&d_counts[v.y], 1);
        atomicAdd(&d_counts[v.z], 1);
        atomicAdd(&d_counts[v.w], 1);
    }
}

__global__ void k_scan() {
    __shared__ int warpsum[32];
    __shared__ int s_carry;
    int tid = threadIdx.x, lane = tid & 31, wid = tid >> 5;
    if (tid == 0) s_carry = 0;
    __syncthreads();
    for (int base = 0; base < N_NODES; base += 4096) {
        int idx = base + tid * 4;
        int4 v = make_int4(0, 0, 0, 0);
        if (idx < N_NODES) v = *(const int4*)&d_counts[idx];
        int s1 = v.x + v.y, s2 = s1 + v.z, s3 = s2 + v.w;
        int sum = s3;
        #pragma unroll
        for (int off = 1; off < 32; off <<= 1) {
            int t = __shfl_up_sync(FULL, sum, off);
            if (lane >= off) sum += t;
        }
        if (lane == 31) warpsum[wid] = sum;
        __syncthreads();
        if (wid == 0) {
            int w = warpsum[lane];
            #pragma unroll
            for (int off = 1; off < 32; off <<= 1) {
                int t = __shfl_up_sync(FULL, w, off);
                if (lane >= off) w += t;
            }
            warpsum[lane] = w;
        }
        __syncthreads();
        int warpoff = (wid == 0) ? 0 : warpsum[wid - 1];
        int carry = s_carry;
        int excl = carry + warpoff + (sum - s3);
        if (idx < N_NODES) {
            int4 o;
            o.x = excl; o.y = excl + v.x; o.z = excl + s1; o.w = excl + s2;
            *(int4*)&d_cursor[idx] = o;
        }
        __syncthreads();
        if (tid == 0) s_carry = carry + warpsum[31];
        __syncthreads();
    }
}

__global__ void k_scatter(const int* __restrict__ src, const int* __restrict__ dst) {
    int e4 = blockIdx.x * blockDim.x + threadIdx.x;
    if (e4 * 4 < N_EDGES) {
        int4 d = ((const int4*)dst)[e4];
        int4 s = ((const int4*)src)[e4];
        int p0 = atomicAdd(&d_cursor[d.x], 1);
        int p1 = atomicAdd(&d_cursor[d.y], 1);
        int p2 = atomicAdd(&d_cursor[d.z], 1);
        int p3 = atomicAdd(&d_cursor[d.w], 1);
        d_col[p0] = s.x;
        d_col[p1] = s.y;
        d_col[p2] = s.z;
        d_col[p3] = s.w;
    }
}

// ---------------- layer-0 projection: y = x @ w1_0 (4-warp cooperative) ----------
__global__ __launch_bounds__(256) void k_proj0(const float* __restrict__ x,
                                               const float* __restrict__ w1) {
    __shared__ float part[2][4][H];
    int tid = threadIdx.x, lane = tid & 31, warp = tid >> 5;
    int grp = warp >> 2, wi = warp & 3;  // 2 groups of 4 warps; group handles 1 node
    float wr[32];
    #pragma unroll
    for (int k = 0; k < 32; k++) wr[k] = w1[(wi * 32 + k) * H + lane];

    const int stride = NBLK * 2;
    const int iters = (N_NODES + stride - 1) / stride;
    int node = blockIdx.x * 2 + grp;
    for (int it = 0; it < iters; it++, node += stride) {
        bool valid = node < N_NODES;
        float acc = 0.f;
        if (valid) {
            float xv = x[(size_t)node * F_IN + wi * 32 + lane];
            #pragma unroll
            for (int k = 0; k < 32; k++)
                acc += __shfl_sync(FULL, xv, k) * wr[k];
        }
        part[grp][wi][lane] = acc;
        __syncthreads();
        if (valid && wi == 0) {
            float s = part[grp][0][lane] + part[grp][1][lane]
                    + part[grp][2][lane] + part[grp][3][lane];
            ((__half*)d_yh)[node * H + lane] = __float2half_rn(s);
        }
        __syncthreads();
    }
}

// ---------------- layers 1-3 projection with folded BN: y = h @ Wf + cf --------
__global__ __launch_bounds__(256) void k_projh(int inSel) {
    int tid = threadIdx.x, lane = tid & 31, warp = tid >> 5;
    float wfc[H];
    #pragma unroll
    for (int k = 0; k < H; k++) wfc[k] = d_Wf[k * H + lane];
    float cfv = d_cf[lane];
    const __half* hin = inSel ? d_hB : d_hA;
    for (int node = blockIdx.x * 8 + warp; node < N_NODES; node += NBLK * 8) {
        float hv = __half2float(hin[node * H + lane]);
        float acc = cfv;
        #pragma unroll
        for (int k = 0; k < H; k++)
            acc += __shfl_sync(FULL, hv, k) * wfc[k];
        ((__half*)d_yh)[node * H + lane] = __float2half_rn(acc);
    }
}

// ---------------- aggregate + MLP2 + relu + BN stats (+ optional pooling) ------
// fp16 gather: row = 64B = 4 chunks of 16B. lane = slot*4 + chunk (8 slots).
// Single node per warp, high occupancy (4 blocks/SM), index prefetch.

#define HACC4(v, Hc) do {                                   \
    Hc[0] = __hadd2(Hc[0], ((const __half2*)&(v))[0]);      \
    Hc[1] = __hadd2(Hc[1], ((const __half2*)&(v))[1]);      \
    Hc[2] = __hadd2(Hc[2], ((const __half2*)&(v))[2]);      \
    Hc[3] = __hadd2(Hc[3], ((const __half2*)&(v))[3]); } while (0)

#define FLUSH4(Hc, F) do { float2 _f;                        \
    _f = __half22float2(Hc[0]); F[0] += _f.x; F[1] += _f.y;  \
    _f = __half22float2(Hc[1]); F[2] += _f.x; F[3] += _f.y;  \
    _f = __half22float2(Hc[2]); F[4] += _f.x; F[5] += _f.y;  \
    _f = __half22float2(Hc[3]); F[6] += _f.x; F[7] += _f.y; } while (0)

#define RPAD 36  // padded row (floats) for conflict-free slot-sum reads

__global__ __launch_bounds__(256, 4) void k_mlp(const float* __restrict__ b1,
                                                const float* __restrict__ w2,
                                                const float* __restrict__ b2,
                                                int outSel, int layer, int doPool,
                                                const int* __restrict__ batch) {
    __shared__ float sw2[H * H];
    __shared__ float sSum[H];
    __shared__ float sSq[H];
    __shared__ float sred[8][8 * RPAD];   // [warp][slot*RPAD + ch]
    int tid = threadIdx.x, lane = tid & 31, warp = tid >> 5;
    for (int i = tid; i < H * H; i += 256) sw2[i] = w2[i];
    if (tid < H) { sSum[tid] = 0.f; sSq[tid] = 0.f; }
    __syncthreads();

    float b1v = b1[lane], b2v = b2[lane];
    __half* hout = outSel ? d_hB : d_hA;
    const __half* selfh = (const __half*)d_yh;

    const int chunk = lane & 3;   // 16B chunk of the row
    const int slot  = lane >> 2;  // neighbor slot 0..7
    const int sbase = slot * RPAD + chunk * 8;
    const int W = NBLK_M * 8;     // total warps
    float bnS = 0.f, bnQ = 0.f;

    for (int node = blockIdx.x * 8 + warp; node < N_NODES; node += W) {
        int deg = d_counts[node];
        int end = d_cursor[node];
        int start = end - deg;

        float F[8] = {0, 0, 0, 0, 0, 0, 0, 0};

        // prefetch first index tile
        int nb = (lane < deg) ? d_col[start + lane] : 0;
        for (int base = 0; base < deg; base += 32) {
            int m = deg - base;
            int nbcur = nb;
            int nrem = m - 32;
            if (nrem > 0)
                nb = (lane < nrem) ? d_col[start + base + 32 + lane] : 0;
            __half2 hz = __float2half2_rn(0.f);
            __half2 Hc[4] = {hz, hz, hz, hz};
            #pragma unroll
            for (int t = 0; t < 32; t += 8) {
                int i = t + slot;
                int j = __shfl_sync(FULL, nbcur, i);
                if (i < m) {
                    uint4 v = d_yh[j * (H / 8) + chunk];
                    HACC4(v, Hc);
                }
            }
            FLUSH4(Hc, F);
        }

        // slot reduction via smem transpose
        *(float4*)&sred[warp][sbase]     = make_float4(F[0], F[1], F[2], F[3]);
        *(float4*)&sred[warp][sbase + 4] = make_float4(F[4], F[5], F[6], F[7]);
        __syncwarp();
        float agg = 0.f;
        #pragma unroll
        for (int s = 0; s < 8; s++)
            agg += sred[warp][s * RPAD + lane];
        __syncwarp();

        float z = agg + __half2float(selfh[node * H + lane]) + b1v;
        float tt = z > 0.f ? z : 0.f;

        // MLP2: 4-way split accumulators
        float ua = 0, ub = 0, uc = 0, ud = 0;
        #pragma unroll
        for (int k = 0; k < H; k += 4) {
            ua += __shfl_sync(FULL, tt, k + 0) * sw2[(k + 0) * H + lane];
            ub += __shfl_sync(FULL, tt, k + 1) * sw2[(k + 1) * H + lane];
            uc += __shfl_sync(FULL, tt, k + 2) * sw2[(k + 2) * H + lane];
            ud += __shfl_sync(FULL, tt, k + 3) * sw2[(k + 3) * H + lane];
        }
        float u = (ua + ub) + (uc + ud) + b2v;
        float h = u > 0.f ? u : 0.f;
        hout[node * H + lane] = __float2half_rn(h);
        bnS += h; bnQ += h * h;
        if (doPool) {
            int b = batch[node];
            atomicAdd(&d_pooled[b * H + lane], h);
            if (lane == 0) atomicAdd(&d_cnt[b], 1.0f);
        }
    }
    atomicAdd(&sSum[lane], bnS);
    atomicAdd(&sSq[lane], bnQ);
    __syncthreads();
    if (tid < H) {
        atomicAdd(&d_sum[layer][tid], sSum[tid]);
        atomicAdd(&d_sq[layer][tid], sSq[tid]);
    }
}

// ---------------- BN fold into next-layer W1 (or stash for head) ----------------
__global__ void k_fold(int layer, const float* __restrict__ gamma,
                       const float* __restrict__ beta,
                       const float* __restrict__ w1next, int isLast) {
    __shared__ float A[H];
    __shared__ float Bc[H];
    int tid = threadIdx.x;
    if (tid < H) {
        float mean = d_sum[layer][tid] / (float)N_NODES;
        float var = d_sq[layer][tid] / (float)N_NODES - mean * mean;
        float a = gamma[tid] * rsqrtf(var + BN_EPS);
        A[tid] = a;
        Bc[tid] = beta[tid] - a * mean;
    }
    __syncthreads();
    if (isLast) {
        if (tid < H) { d_A3[tid] = A[tid]; d_Bc3[tid] = Bc[tid]; }
    } else {
        if (tid < H * H) {
            int k = tid >> 5;
            d_Wf[tid] = A[k] * w1next[tid];
        }
        if (tid < H) {
            float c = 0.f;
            for (int k = 0; k < H; k++) c += Bc[k] * w1next[k * H + tid];
            d_cf[tid] = c;
        }
    }
}

// ---------------- pooling finalize + fc head + log_softmax ----------------
__global__ void k_head(const float* __restrict__ fc1w, const float* __restrict__ fc1b,
                       const float* __restrict__ fc2w, const float* __restrict__ fc2b,
                       float* __restrict__ out) {
    __shared__ float s1[H * H];
    __shared__ float s2[H * C_OUT];
    __shared__ float sb1[H], sb2[C_OUT], sA[H], sB[H];
    int tid = threadIdx.x;
    for (int i = tid; i < H * H; i += blockDim.x) s1[i] = fc1w[i];
    for (int i = tid; i < H * C_OUT; i += blockDim.x) s2[i] = fc2w[i];
    if (tid < H) { sb1[tid] = fc1b[tid]; sA[tid] = d_A3[tid]; sB[tid] = d_Bc3[tid]; }
    if (tid < C_OUT) sb2[tid] = fc2b[tid];
    __syncthreads();
    if (tid >= B_GR) return;
    float cnt = d_cnt[tid];
    if (cnt < 1.f) cnt = 1.f;
    float m[H];
    #pragma unroll
    for (int k = 0; k < H; k++)
        m[k] = sA[k] * (d_pooled[tid * H + k] / cnt) + sB[k];
    float t[H];
    #pragma unroll
    for (int j = 0; j < H; j++) {
        float acc = sb1[j];
        #pragma unroll
        for (int k = 0; k < H; k++) acc += m[k] * s1[k * H + j];
        t[j] = acc > 0.f ? acc : 0.f;
    }
    float lg[C_OUT];
    float mx = -1e30f;
    #pragma unroll
    for (int c = 0; c < C_OUT; c++) {
        float acc = sb2[c];
        #pragma unroll
        for (int j = 0; j < H; j++) acc += t[j] * s2[j * C_OUT + c];
        lg[c] = acc;
        if (acc > mx) mx = acc;
    }
    float se = 0.f;
    #pragma unroll
    for (int c = 0; c < C_OUT; c++) se += expf(lg[c] - mx);
    float lse = mx + logf(se);
    #pragma unroll
    for (int c = 0; c < C_OUT; c++) out[tid * C_OUT + c] = lg[c] - lse;
}

// ---------------- launcher ----------------
extern "C" void kernel_launch(void* const* d_in, const int* in_sizes, int n_in,
                              void* d_out, int out_size) {
    const float* x     = (const float*)d_in[0];
    const int*   ei    = (const int*)d_in[1];
    const int*   batch = (const int*)d_in[2];
    const float* w1_0  = (const float*)d_in[3];
    const float* b1_0  = (const float*)d_in[4];
    const float* w2_0  = (const float*)d_in[5];
    const float* b2_0  = (const float*)d_in[6];
    const float* g_0   = (const float*)d_in[7];
    const float* be_0  = (const float*)d_in[8];
    const float* w1s   = (const float*)d_in[9];
    const float* b1s   = (const float*)d_in[10];
    const float* w2s   = (const float*)d_in[11];
    const float* b2s   = (const float*)d_in[12];
    const float* gs    = (const float*)d_in[13];
    const float* bes   = (const float*)d_in[14];
    const float* fc1w  = (const float*)d_in[15];
    const float* fc1b  = (const float*)d_in[16];
    const float* fc2w  = (const float*)d_in[17];
    const float* fc2b  = (const float*)d_in[18];
    float* out = (float*)d_out;

    const int* src = ei;
    const int* dst = ei + N_EDGES;

    const int eb4 = (N_EDGES / 4 + 255) / 256;

    k_zero<<<(N_NODES + 255) / 256, 256>>>();
    k_hist<<<eb4, 256>>>(dst);
    k_scan<<<1, 1024>>>();
    k_scatter<<<eb4, 256>>>(src, dst);

    // layer 0: (F_IN -> H), BN
    k_proj0<<<NBLK, 256>>>(x, w1_0);
    k_mlp<<<NBLK_M, 256>>>(b1_0, w2_0, b2_0, /*outSel=*/0, /*layer=*/0, /*pool=*/0, batch);
    k_fold<<<1, 1024>>>(0, g_0, be_0, w1s + 0 * H * H, 0);

    // layer 1
    k_projh<<<NBLK, 256>>>(/*inSel=*/0);
    k_mlp<<<NBLK_M, 256>>>(b1s + 0 * H, w2s + 0 * H * H, b2s + 0 * H, 1, 1, 0, batch);
    k_fold<<<1, 1024>>>(1, gs + 0 * H, bes + 0 * H, w1s + 1 * H * H, 0);

    // layer 2
    k_projh<<<NBLK, 256>>>(1);
    k_mlp<<<NBLK_M, 256>>>(b1s + 1 * H, w2s + 1 * H * H, b2s + 1 * H, 0, 2, 0, batch);
    k_fold<<<1, 1024>>>(2, gs + 1 * H, bes + 1 * H, w1s + 2 * H * H, 0);

    // layer 3 (+ pooling; final BN folded into head affine)
    k_projh<<<NBLK, 256>>>(0);
    k_mlp<<<NBLK_M, 256>>>(b1s + 2 * H, w2s + 2 * H * H, b2s + 2 * H, 1, 3, 1, batch);
    k_fold<<<1, 1024>>>(3, gs + 2 * H, bes + 2 * H, w1s, 1);

    k_head<<<1, 128>>>(fc1w, fc1b, fc2w, fc2b, out);
}